// round 15
// baseline (speedup 1.0000x reference)
#include <cuda_runtime.h>
#include <cuda_fp16.h>
#include <math.h>
#include <stdint.h>

#define T_SEQ 2048
#define HID 4096
#define NH 32
#define NKV 8
#define HD 128

// ---------------- scratch (__device__ globals; no allocations) -------------
__device__ float  g_Q  [(size_t)T_SEQ * NH * HD];     // fp32 Q (pre-rope)
__device__ float  g_K  [(size_t)T_SEQ * NKV * HD];    // fp32 K (pre-rope)
__device__ __half g_xh [(size_t)T_SEQ * HID];
__device__ __half g_Wqh[(size_t)NH * HD * HID];
__device__ __half g_Wkh[(size_t)NKV * HD * HID];
__device__ __half g_Wvh[(size_t)NKV * HD * HID];
__device__ __half g_Woh[(size_t)HID * NH * HD];
__device__ __half g_Qh [(size_t)T_SEQ * NH * HD];     // roped, scaled log2e/sqrt(128)
__device__ __half g_Kh [(size_t)T_SEQ * NKV * HD];    // roped
__device__ __half g_VTh[(size_t)NKV * HD * T_SEQ];    // V^T [h][d][t]
__device__ __half g_Oh [(size_t)T_SEQ * NH * HD];

__device__ __forceinline__ uint32_t smem_u32(const void* p) {
    uint32_t a;
    asm("{ .reg .u64 t; cvta.to.shared.u64 t, %1; cvt.u32.u64 %0, t; }"
        : "=r"(a) : "l"(p));
    return a;
}
__device__ __forceinline__ unsigned h2u(float a, float b) {
    __half2 h = __floats2half2_rn(a, b);
    return *reinterpret_cast<unsigned*>(&h);
}
__device__ __forceinline__ unsigned ex2_h2(unsigned x) {
    unsigned r;
    asm("ex2.approx.f16x2 %0, %1;" : "=r"(r) : "r"(x));
    return r;
}
__device__ __forceinline__ float ex2_f32(float x) {
    float r;
    asm("ex2.approx.f32 %0, %1;" : "=f"(r) : "f"(x));
    return r;
}

#define MMA_F16(d, a0,a1,a2,a3, b0,b1)                                        \
    asm volatile(                                                             \
        "mma.sync.aligned.m16n8k16.row.col.f32.f16.f16.f32 "                  \
        "{%0,%1,%2,%3}, {%4,%5,%6,%7}, {%8,%9}, {%0,%1,%2,%3};"               \
        : "+f"((d)[0]), "+f"((d)[1]), "+f"((d)[2]), "+f"((d)[3])              \
        : "r"(a0), "r"(a1), "r"(a2), "r"(a3), "r"(b0), "r"(b1))

#define LDSM4(r0, r1, r2, r3, addr)                                           \
    asm volatile("ldmatrix.sync.aligned.m8n8.x4.shared.b16 {%0,%1,%2,%3}, [%4];" \
        : "=r"(r0), "=r"(r1), "=r"(r2), "=r"(r3) : "r"(addr))

#define CP_ASYNC16(dst, src) \
    asm volatile("cp.async.cg.shared.global [%0], [%1], 16;" :: "r"(dst), "l"(src))
#define CP_COMMIT()  asm volatile("cp.async.commit_group;" ::: "memory")
#define CP_WAIT2()   asm volatile("cp.async.wait_group 2;" ::: "memory")
#define CP_WAIT0()   asm volatile("cp.async.wait_group 0;" ::: "memory")

// ---------------------------------------------------------------------------
// Fused fp32 -> fp16 conversion of all 5 inputs in ONE launch.
// ---------------------------------------------------------------------------
#define SEG_X  1048576L
#define SEG_WQ (SEG_X + 2097152L)
#define SEG_WK (SEG_WQ + 524288L)
#define SEG_WV (SEG_WK + 524288L)

__global__ void cvt_all(const float4* __restrict__ x,  const float4* __restrict__ wq,
                        const float4* __restrict__ wk, const float4* __restrict__ wv,
                        const float4* __restrict__ wo,
                        uint4* __restrict__ xh,  uint4* __restrict__ wqh,
                        uint4* __restrict__ wkh, uint4* __restrict__ wvh,
                        uint4* __restrict__ woh)
{
    const long i = (long)blockIdx.x * blockDim.x + threadIdx.x;
    const float4* in;
    uint4* out;
    long off;
    if (i < SEG_X)       { in = x;  out = xh;  off = 0; }
    else if (i < SEG_WQ) { in = wq; out = wqh; off = SEG_X; }
    else if (i < SEG_WK) { in = wk; out = wkh; off = SEG_WQ; }
    else if (i < SEG_WV) { in = wv; out = wvh; off = SEG_WK; }
    else                 { in = wo; out = woh; off = SEG_WV; }
    const long j = i - off;
    float4 v0 = in[2 * j];
    float4 v1 = in[2 * j + 1];
    uint4 o;
    o.x = h2u(v0.x, v0.y);
    o.y = h2u(v0.z, v0.w);
    o.z = h2u(v1.x, v1.y);
    o.w = h2u(v1.z, v1.w);
    out[j] = o;
}

// ---------------------------------------------------------------------------
// FP16 GEMM core: block 128x256, kc 32, 8 warps 2x4 each 64x64 m16n8k16,
// 3-stage cp.async, HSTR=40 pad. Fragment loads via ldmatrix.x4.
// ---------------------------------------------------------------------------
#define HSTR 40
#define STG_HALVES ((128 + 256) * HSTR)
#define STG_BYTES  (STG_HALVES * 2)
#define GEMM_SMEM  (3 * STG_BYTES)
#define ROW16_B (16 * HSTR * 2)           // bytes per 16 smem rows

__device__ __forceinline__ void gemm_core(
    const __half* __restrict__ A, const __half* __restrict__ B, void* __restrict__ Cv,
    int K, int lda, int ldb, int ldc, int bm, int bn, int half_out)
{
    extern __shared__ __half smh[];
    const uint32_t smb = smem_u32(smh);

    const int tid  = threadIdx.x;
    const int lane = tid & 31;
    const int w    = tid >> 5;
    const int g    = lane >> 2;
    const int t    = lane & 3;
    const int wm   = (w >> 2) * 64;
    const int wn   = (w & 3) * 64;

    // ldmatrix per-lane base offsets (bytes) within a stage
    const uint32_t a_ldsm = ((uint32_t)((wm + ((lane >> 3) & 1) * 8 + (lane & 7)) * HSTR
                                        + ((lane >> 4) & 1) * 8)) * 2u;
    const uint32_t b_ldsm = ((uint32_t)((128 + wn + ((lane >> 4) & 1) * 8 + (lane & 7)) * HSTR
                                        + ((lane >> 3) & 1) * 8)) * 2u;

    float acc[4][8][4];
    #pragma unroll
    for (int mi = 0; mi < 4; mi++)
        #pragma unroll
        for (int ni = 0; ni < 8; ni++)
            #pragma unroll
            for (int q = 0; q < 4; q++) acc[mi][ni][q] = 0.0f;

    const int nch = K >> 5;

    #define GFILL(stage, k0) do {                                              \
        const uint32_t sb = smb + (stage) * STG_BYTES;                          \
        _Pragma("unroll")                                                       \
        for (int p = 0; p < 2; p++) {                                           \
            const int cid = tid + 256 * p;                                      \
            const int r = cid >> 2, c = (cid & 3) * 8;                          \
            CP_ASYNC16(sb + (uint32_t)(r * HSTR + c) * 2u,                      \
                       A + (size_t)(bm + r) * lda + (k0) + c);                  \
        }                                                                       \
        _Pragma("unroll")                                                       \
        for (int p = 0; p < 4; p++) {                                           \
            const int cid = tid + 256 * p;                                      \
            const int r = cid >> 2, c = (cid & 3) * 8;                          \
            CP_ASYNC16(sb + (uint32_t)((128 + r) * HSTR + c) * 2u,              \
                       B + (size_t)(bn + r) * ldb + (k0) + c);                  \
        }                                                                       \
    } while (0)

    GFILL(0, 0);  CP_COMMIT();
    GFILL(1, 32); CP_COMMIT();
    GFILL(2, 64); CP_COMMIT();

    for (int i = 0; i < nch; i++) {
        const int s = i - (i / 3) * 3;
        CP_WAIT2();
        __syncthreads();

        const uint32_t sb = smb + s * STG_BYTES;

        #pragma unroll
        for (int ks = 0; ks < 2; ks++) {
            const uint32_t ob = ks * 32;   // 16 halves
            unsigned af[4][4], bf[8][2];
            #pragma unroll
            for (int mi = 0; mi < 4; mi++)
                LDSM4(af[mi][0], af[mi][1], af[mi][2], af[mi][3],
                      sb + a_ldsm + mi * ROW16_B + ob);
            #pragma unroll
            for (int p = 0; p < 4; p++)
                LDSM4(bf[2 * p][0], bf[2 * p][1], bf[2 * p + 1][0], bf[2 * p + 1][1],
                      sb + b_ldsm + p * ROW16_B + ob);
            #pragma unroll
            for (int mi = 0; mi < 4; mi++)
                #pragma unroll
                for (int ni = 0; ni < 8; ni++)
                    MMA_F16(acc[mi][ni], af[mi][0], af[mi][1], af[mi][2], af[mi][3],
                            bf[ni][0], bf[ni][1]);
        }
        __syncthreads();

        if (i + 3 < nch) GFILL(s, (i + 3) * 32);
        CP_COMMIT();
    }
    #undef GFILL

    if (half_out) {
        __half* C = (__half*)Cv;
        #pragma unroll
        for (int mi = 0; mi < 4; mi++) {
            const size_t r0 = (size_t)(bm + wm + mi * 16 + g) * ldc + bn + wn;
            const size_t r1 = r0 + (size_t)8 * ldc;
            #pragma unroll
            for (int ni = 0; ni < 8; ni++) {
                const int cc = ni * 8 + 2 * t;
                *reinterpret_cast<unsigned*>(C + r0 + cc) = h2u(acc[mi][ni][0], acc[mi][ni][1]);
                *reinterpret_cast<unsigned*>(C + r1 + cc) = h2u(acc[mi][ni][2], acc[mi][ni][3]);
            }
        }
    } else {
        float* C = (float*)Cv;
        #pragma unroll
        for (int mi = 0; mi < 4; mi++) {
            const size_t r0 = (size_t)(bm + wm + mi * 16 + g) * ldc + bn + wn;
            const size_t r1 = r0 + (size_t)8 * ldc;
            #pragma unroll
            for (int ni = 0; ni < 8; ni++) {
                const int cc = ni * 8 + 2 * t;
                *reinterpret_cast<float2*>(C + r0 + cc) = make_float2(acc[mi][ni][0], acc[mi][ni][1]);
                *reinterpret_cast<float2*>(C + r1 + cc) = make_float2(acc[mi][ni][2], acc[mi][ni][3]);
            }
        }
    }
}

__global__ __launch_bounds__(256)
void gemm_h(const __half* __restrict__ A, const __half* __restrict__ B,
            void* __restrict__ C, int K, int lda, int ldb, int ldc, int half_out)
{
    gemm_core(A, B, C, K, lda, ldb, ldc, blockIdx.y * 128, blockIdx.x * 256, half_out);
}

__global__ __launch_bounds__(256)
void gemm_kv(const __half* __restrict__ xh, const __half* __restrict__ Wkh,
             const __half* __restrict__ Wvh, float* __restrict__ K, __half* __restrict__ VT)
{
    if (blockIdx.y == 0)
        gemm_core(xh, Wkh, K, HID, HID, HID, NKV * HD,
                  (blockIdx.x >> 2) * 128, (blockIdx.x & 3) * 256, 0);
    else
        gemm_core(Wvh, xh, VT, HID, HID, HID, T_SEQ,
                  (blockIdx.x >> 3) * 128, (blockIdx.x & 7) * 256, 1);
}

// ---------------------------------------------------------------------------
// Fused llama3-RoPE + fp16 conversion for Q AND K in one launch
// ---------------------------------------------------------------------------
__global__ void rope_qk(const float* __restrict__ Qin, __half* __restrict__ Qout,
                        const float* __restrict__ Kin, __half* __restrict__ Kout,
                        float qscale)
{
    const int t  = blockIdx.x;
    const int hy = blockIdx.y * 4 + threadIdx.y;
    const int i  = threadIdx.x;   // 0..63

    const float e   = (float)i * (1.0f / 64.0f);
    const float inv = exp2f(-18.931568569324174f * e);   // log2(500000)
    const float wavelen = 6.2831853071795865f / inv;
    float f;
    if (wavelen > 8192.0f) {
        f = inv * 0.125f;
    } else if (wavelen < 2048.0f) {
        f = inv;
    } else {
        const float smooth = (8192.0f / wavelen - 1.0f) * (1.0f / 3.0f);
        f = (1.0f - smooth) * 0.125f * inv + smooth * inv;
    }

    float s, c;
    sincosf((float)t * f, &s, &c);

    const float* in;
    __half* out;
    float scale;
    size_t base;
    if (hy < NH) {
        base  = (size_t)t * (NH * HD) + hy * HD;
        in    = Qin;  out = Qout;  scale = qscale;
    } else {
        const int h = hy - NH;
        base  = (size_t)t * (NKV * HD) + h * HD;
        in    = Kin;  out = Kout;  scale = 1.0f;
    }

    const float lo = in[base + i];
    const float hi = in[base + i + 64];
    out[base + i]      = __float2half_rn((lo * c - hi * s) * scale);
    out[base + i + 64] = __float2half_rn((hi * c + lo * s) * scale);
}

// ---------------------------------------------------------------------------
// Flash attention — R13 structure (3 tiles, 2 CTAs/SM, single KV group) +
// warp-uniform skip-rescale fast path (bit-identical math). ldmatrix frags,
// Q frags hoisted, log2 softmax, row sums via all-ones MMA. Q pre-scaled.
// ---------------------------------------------------------------------------
#define FH 136
#define FLASH_SMEM (3 * 128 * FH * 2)     // 104448 B -> 2 CTAs/SM
#define ONES_H2 0x3C003C00u
#define LDSM_PSTRIDE (16 * FH * 2)

__global__ __launch_bounds__(256)
void flash_attn(const __half* __restrict__ Qg, const __half* __restrict__ Kg,
                const __half* __restrict__ VTg, __half* __restrict__ Og)
{
    extern __shared__ __half fsm[];
    __half* Qs = fsm;
    const uint32_t qb = smem_u32(Qs);
    const uint32_t kb = qb + 128 * FH * 2;
    const uint32_t vb = kb + 128 * FH * 2;

    const int h  = blockIdx.y;
    const int ib = gridDim.x - 1 - blockIdx.x;   // heavy blocks first
    const int kv = h >> 2;
    const int tid  = threadIdx.x;
    const int lane = tid & 31;
    const int w    = tid >> 5;
    const int g    = lane >> 2;
    const int t    = lane & 3;
    const int wr   = w * 16;

    const uint32_t a_off = ((uint32_t)(wr + ((lane >> 3) & 1) * 8 + (lane & 7)) * FH
                            + ((lane >> 4) & 1) * 8) * 2u;
    const uint32_t b_off = ((uint32_t)(((lane >> 4) & 1) * 8 + (lane & 7)) * FH
                            + ((lane >> 3) & 1) * 8) * 2u;

    // Q tile prefetch, then hoist Q fragments into registers
    #pragma unroll
    for (int p = 0; p < 8; p++) {
        const int fidx = tid + 256 * p;
        const int r = fidx >> 4, c = (fidx & 15) * 8;
        CP_ASYNC16(qb + (uint32_t)(r * FH + c) * 2u,
                   Qg + (size_t)(ib * 128 + r) * (NH * HD) + h * HD + c);
    }
    CP_COMMIT();
    CP_WAIT0();
    __syncthreads();

    unsigned qf[8][4];
    #pragma unroll
    for (int ks = 0; ks < 8; ks++)
        LDSM4(qf[ks][0], qf[ks][1], qf[ks][2], qf[ks][3], qb + a_off + ks * 32);

    float m0 = -1e30f, m1 = -1e30f, l0 = 0.0f, l1 = 0.0f;
    float o[16][4];
    #pragma unroll
    for (int ni = 0; ni < 16; ni++)
        #pragma unroll
        for (int q = 0; q < 4; q++) o[ni][q] = 0.0f;

    for (int j = 0; j <= ib; j++) {
        __syncthreads();   // prior iteration done reading Ks/Vs
        #pragma unroll
        for (int p = 0; p < 8; p++) {
            const int fidx = tid + 256 * p;
            const int r = fidx >> 4, c = (fidx & 15) * 8;
            CP_ASYNC16(kb + (uint32_t)(r * FH + c) * 2u,
                       Kg + (size_t)(j * 128 + r) * (NKV * HD) + kv * HD + c);
            CP_ASYNC16(vb + (uint32_t)(r * FH + c) * 2u,
                       VTg + ((size_t)kv * HD + r) * T_SEQ + j * 128 + c);
        }
        CP_COMMIT();
        CP_WAIT0();
        __syncthreads();

        // S = Q*K^T in log2 units
        float sc[16][4];
        #pragma unroll
        for (int ni = 0; ni < 16; ni++)
            #pragma unroll
            for (int q = 0; q < 4; q++) sc[ni][q] = 0.0f;

        #pragma unroll
        for (int ks = 0; ks < 8; ks++) {
            unsigned bf[16][2];
            #pragma unroll
            for (int p = 0; p < 8; p++)
                LDSM4(bf[2 * p][0], bf[2 * p][1], bf[2 * p + 1][0], bf[2 * p + 1][1],
                      kb + b_off + p * LDSM_PSTRIDE + ks * 32);
            #pragma unroll
            for (int ni = 0; ni < 16; ni++)
                MMA_F16(sc[ni], qf[ks][0], qf[ks][1], qf[ks][2], qf[ks][3],
                        bf[ni][0], bf[ni][1]);
        }

        // Causal mask on the diagonal block
        if (j == ib) {
            #pragma unroll
            for (int ni = 0; ni < 16; ni++) {
                const int c0 = ni * 8 + 2 * t;
                const int r0 = wr + g, r1 = wr + g + 8;
                if (c0     > r0) sc[ni][0] = -1e30f;
                if (c0 + 1 > r0) sc[ni][1] = -1e30f;
                if (c0     > r1) sc[ni][2] = -1e30f;
                if (c0 + 1 > r1) sc[ni][3] = -1e30f;
            }
        }

        // Row max (log2 domain)
        float bm0 = -1e30f, bm1 = -1e30f;
        #pragma unroll
        for (int ni = 0; ni < 16; ni++) {
            bm0 = fmaxf(bm0, fmaxf(sc[ni][0], sc[ni][1]));
            bm1 = fmaxf(bm1, fmaxf(sc[ni][2], sc[ni][3]));
        }
        bm0 = fmaxf(bm0, __shfl_xor_sync(0xffffffffu, bm0, 1));
        bm0 = fmaxf(bm0, __shfl_xor_sync(0xffffffffu, bm0, 2));
        bm1 = fmaxf(bm1, __shfl_xor_sync(0xffffffffu, bm1, 1));
        bm1 = fmaxf(bm1, __shfl_xor_sync(0xffffffffu, bm1, 2));

        // Skip-rescale fast path: if no row's max grew, al == 1 exactly.
        const bool need = __any_sync(0xffffffffu, (bm0 > m0) || (bm1 > m1));
        float mn0 = m0, mn1 = m1;
        if (need) {
            mn0 = fmaxf(m0, bm0);
            mn1 = fmaxf(m1, bm1);
            const float al0 = ex2_f32(m0 - mn0), al1 = ex2_f32(m1 - mn1);
            #pragma unroll
            for (int ni = 0; ni < 16; ni++) {
                o[ni][0] *= al0; o[ni][1] *= al0;
                o[ni][2] *= al1; o[ni][3] *= al1;
            }
            l0 *= al0; l1 *= al1;
            m0 = mn0; m1 = mn1;
        }

        // P = 2^(s-m), pairwise fp16 MUFU
        unsigned ph[16][2];
        #pragma unroll
        for (int ni = 0; ni < 16; ni++) {
            ph[ni][0] = ex2_h2(h2u(sc[ni][0] - mn0, sc[ni][1] - mn0));
            ph[ni][1] = ex2_h2(h2u(sc[ni][2] - mn1, sc[ni][3] - mn1));
        }

        // O += P*V (V frags via ldmatrix.x4); row sums via all-ones MMA
        float ls[4] = {0.0f, 0.0f, 0.0f, 0.0f};
        #pragma unroll
        for (int kt = 0; kt < 8; kt++) {
            const unsigned a0 = ph[2 * kt    ][0];
            const unsigned a1 = ph[2 * kt    ][1];
            const unsigned a2 = ph[2 * kt + 1][0];
            const unsigned a3 = ph[2 * kt + 1][1];
            MMA_F16(ls, a0, a1, a2, a3, ONES_H2, ONES_H2);
            unsigned bf[16][2];
            #pragma unroll
            for (int p = 0; p < 8; p++)
                LDSM4(bf[2 * p][0], bf[2 * p][1], bf[2 * p + 1][0], bf[2 * p + 1][1],
                      vb + b_off + p * LDSM_PSTRIDE + kt * 32);
            #pragma unroll
            for (int ni = 0; ni < 16; ni++)
                MMA_F16(o[ni], a0, a1, a2, a3, bf[ni][0], bf[ni][1]);
        }
        l0 += ls[0];
        l1 += ls[2];
    }

    // Epilogue
    const float i0 = 1.0f / l0, i1 = 1.0f / l1;
    const size_t r0 = (size_t)(ib * 128 + wr + g) * (NH * HD) + h * HD;
    const size_t r1 = r0 + (size_t)8 * (NH * HD);
    #pragma unroll
    for (int ni = 0; ni < 16; ni++) {
        const int cc = ni * 8 + 2 * t;
        *reinterpret_cast<unsigned*>(Og + r0 + cc) = h2u(o[ni][0] * i0, o[ni][1] * i0);
        *reinterpret_cast<unsigned*>(Og + r1 + cc) = h2u(o[ni][2] * i1, o[ni][3] * i1);
    }
}

// ---------------------------------------------------------------------------
extern "C" void kernel_launch(void* const* d_in, const int* in_sizes, int n_in,
                              void* d_out, int out_size)
{
    const float* x  = (const float*)d_in[0];
    const float* Wq = (const float*)d_in[1];
    const float* Wk = (const float*)d_in[2];
    const float* Wv = (const float*)d_in[3];
    const float* Wo = (const float*)d_in[4];
    float* out = (float*)d_out;

    float *Q, *K;
    __half *xh, *Wqh, *Wkh, *Wvh, *Woh, *Qh, *Kh, *VTh, *Oh;
    cudaGetSymbolAddress((void**)&Q,   g_Q);
    cudaGetSymbolAddress((void**)&K,   g_K);
    cudaGetSymbolAddress((void**)&xh,  g_xh);
    cudaGetSymbolAddress((void**)&Wqh, g_Wqh);
    cudaGetSymbolAddress((void**)&Wkh, g_Wkh);
    cudaGetSymbolAddress((void**)&Wvh, g_Wvh);
    cudaGetSymbolAddress((void**)&Woh, g_Woh);
    cudaGetSymbolAddress((void**)&Qh,  g_Qh);
    cudaGetSymbolAddress((void**)&Kh,  g_Kh);
    cudaGetSymbolAddress((void**)&VTh, g_VTh);
    cudaGetSymbolAddress((void**)&Oh,  g_Oh);

    // All fp16 conversions in one launch
    cvt_all<<<24576, 256>>>((const float4*)x, (const float4*)Wq, (const float4*)Wk,
                            (const float4*)Wv, (const float4*)Wo,
                            (uint4*)xh, (uint4*)Wqh, (uint4*)Wkh, (uint4*)Wvh, (uint4*)Woh);

    cudaFuncSetAttribute(gemm_h,  cudaFuncAttributeMaxDynamicSharedMemorySize, GEMM_SMEM);
    cudaFuncSetAttribute(gemm_kv, cudaFuncAttributeMaxDynamicSharedMemorySize, GEMM_SMEM);
    cudaFuncSetAttribute(flash_attn, cudaFuncAttributeMaxDynamicSharedMemorySize, FLASH_SMEM);

    // Q = x*Wq^T (fp32 out, rope wants fp32)
    gemm_h<<<dim3(16, 16), 256, GEMM_SMEM>>>(xh, Wqh, Q, HID, HID, HID, 4096, 0);
    // K = x*Wk^T (fp32) and VT = Wv*x^T (fp16), fused
    gemm_kv<<<dim3(64, 2), 256, GEMM_SMEM>>>(xh, Wkh, Wvh, K, VTh);

    // RoPE (Q and K) fused with fp16 conversion; Q scale = log2(e)/sqrt(128)
    rope_qk<<<dim3(T_SEQ, (NH + NKV) / 4), dim3(64, 4)>>>(Q, Qh, K, Kh, 0.12751744f);

    // Fused causal attention
    flash_attn<<<dim3(16, NH), 256, FLASH_SMEM>>>(Qh, Kh, VTh, Oh);

    // out = O*Wo^T (fp32 out)
    gemm_h<<<dim3(16, 16), 256, GEMM_SMEM>>>(Oh, Woh, out, 4096, 4096, 4096, HID, 0);
}

// round 16
// speedup vs baseline: 1.4657x; 1.4657x over previous
#include <cuda_runtime.h>
#include <cuda_fp16.h>
#include <math.h>
#include <stdint.h>

#define T_SEQ 2048
#define HID 4096
#define NH 32
#define NKV 8
#define HD 128

// ---------------- scratch (__device__ globals; no allocations) -------------
__device__ float  g_Q  [(size_t)T_SEQ * NH * HD];     // fp32 Q (pre-rope)
__device__ float  g_K  [(size_t)T_SEQ * NKV * HD];    // fp32 K (pre-rope)
__device__ __half g_xh [(size_t)T_SEQ * HID];
__device__ __half g_Wqh[(size_t)NH * HD * HID];
__device__ __half g_Wkh[(size_t)NKV * HD * HID];
__device__ __half g_Wvh[(size_t)NKV * HD * HID];
__device__ __half g_Woh[(size_t)HID * NH * HD];
__device__ __half g_Qh [(size_t)T_SEQ * NH * HD];     // roped, scaled log2e/sqrt(128)
__device__ __half g_Kh [(size_t)T_SEQ * NKV * HD];    // roped
__device__ __half g_VTh[(size_t)NKV * HD * T_SEQ];    // V^T [h][d][t]
__device__ __half g_Oh [(size_t)T_SEQ * NH * HD];

__device__ __forceinline__ uint32_t smem_u32(const void* p) {
    uint32_t a;
    asm("{ .reg .u64 t; cvta.to.shared.u64 t, %1; cvt.u32.u64 %0, t; }"
        : "=r"(a) : "l"(p));
    return a;
}
__device__ __forceinline__ unsigned h2u(float a, float b) {
    __half2 h = __floats2half2_rn(a, b);
    return *reinterpret_cast<unsigned*>(&h);
}
__device__ __forceinline__ unsigned ex2_h2(unsigned x) {
    unsigned r;
    asm("ex2.approx.f16x2 %0, %1;" : "=r"(r) : "r"(x));
    return r;
}
__device__ __forceinline__ float ex2_f32(float x) {
    float r;
    asm("ex2.approx.f32 %0, %1;" : "=f"(r) : "f"(x));
    return r;
}

#define MMA_F16(d, a0,a1,a2,a3, b0,b1)                                        \
    asm volatile(                                                             \
        "mma.sync.aligned.m16n8k16.row.col.f32.f16.f16.f32 "                  \
        "{%0,%1,%2,%3}, {%4,%5,%6,%7}, {%8,%9}, {%0,%1,%2,%3};"               \
        : "+f"((d)[0]), "+f"((d)[1]), "+f"((d)[2]), "+f"((d)[3])              \
        : "r"(a0), "r"(a1), "r"(a2), "r"(a3), "r"(b0), "r"(b1))

#define LDSM4(r0, r1, r2, r3, addr)                                           \
    asm volatile("ldmatrix.sync.aligned.m8n8.x4.shared.b16 {%0,%1,%2,%3}, [%4];" \
        : "=r"(r0), "=r"(r1), "=r"(r2), "=r"(r3) : "r"(addr))

#define CP_ASYNC16(dst, src) \
    asm volatile("cp.async.cg.shared.global [%0], [%1], 16;" :: "r"(dst), "l"(src))
#define CP_COMMIT()  asm volatile("cp.async.commit_group;" ::: "memory")
#define CP_WAIT2()   asm volatile("cp.async.wait_group 2;" ::: "memory")
#define CP_WAIT0()   asm volatile("cp.async.wait_group 0;" ::: "memory")

// ---------------------------------------------------------------------------
// Fused fp32 -> fp16 conversion of all 5 inputs in ONE launch.
// ---------------------------------------------------------------------------
#define SEG_X  1048576L
#define SEG_WQ (SEG_X + 2097152L)
#define SEG_WK (SEG_WQ + 524288L)
#define SEG_WV (SEG_WK + 524288L)

__global__ void cvt_all(const float4* __restrict__ x,  const float4* __restrict__ wq,
                        const float4* __restrict__ wk, const float4* __restrict__ wv,
                        const float4* __restrict__ wo,
                        uint4* __restrict__ xh,  uint4* __restrict__ wqh,
                        uint4* __restrict__ wkh, uint4* __restrict__ wvh,
                        uint4* __restrict__ woh)
{
    const long i = (long)blockIdx.x * blockDim.x + threadIdx.x;
    const float4* in;
    uint4* out;
    long off;
    if (i < SEG_X)       { in = x;  out = xh;  off = 0; }
    else if (i < SEG_WQ) { in = wq; out = wqh; off = SEG_X; }
    else if (i < SEG_WK) { in = wk; out = wkh; off = SEG_WQ; }
    else if (i < SEG_WV) { in = wv; out = wvh; off = SEG_WK; }
    else                 { in = wo; out = woh; off = SEG_WV; }
    const long j = i - off;
    float4 v0 = in[2 * j];
    float4 v1 = in[2 * j + 1];
    uint4 o;
    o.x = h2u(v0.x, v0.y);
    o.y = h2u(v0.z, v0.w);
    o.z = h2u(v1.x, v1.y);
    o.w = h2u(v1.z, v1.w);
    out[j] = o;
}

// ---------------------------------------------------------------------------
// FP16 GEMM core (R13 verbatim — scalar fragment LDS, at HMMA pipe floor)
// ---------------------------------------------------------------------------
#define HSTR 40
#define STG_HALVES ((128 + 256) * HSTR)
#define STG_BYTES  (STG_HALVES * 2)
#define GEMM_SMEM  (3 * STG_BYTES)

__device__ __forceinline__ void gemm_core(
    const __half* __restrict__ A, const __half* __restrict__ B, void* __restrict__ Cv,
    int K, int lda, int ldb, int ldc, int bm, int bn, int half_out)
{
    extern __shared__ __half smh[];
    const uint32_t smb = smem_u32(smh);

    const int tid  = threadIdx.x;
    const int lane = tid & 31;
    const int w    = tid >> 5;
    const int g    = lane >> 2;
    const int t    = lane & 3;
    const int wm   = (w >> 2) * 64;
    const int wn   = (w & 3) * 64;

    float acc[4][8][4];
    #pragma unroll
    for (int mi = 0; mi < 4; mi++)
        #pragma unroll
        for (int ni = 0; ni < 8; ni++)
            #pragma unroll
            for (int q = 0; q < 4; q++) acc[mi][ni][q] = 0.0f;

    const int nch = K >> 5;

    #define GFILL(stage, k0) do {                                              \
        const uint32_t sb = smb + (stage) * STG_BYTES;                          \
        _Pragma("unroll")                                                       \
        for (int p = 0; p < 2; p++) {                                           \
            const int cid = tid + 256 * p;                                      \
            const int r = cid >> 2, c = (cid & 3) * 8;                          \
            CP_ASYNC16(sb + (uint32_t)(r * HSTR + c) * 2u,                      \
                       A + (size_t)(bm + r) * lda + (k0) + c);                  \
        }                                                                       \
        _Pragma("unroll")                                                       \
        for (int p = 0; p < 4; p++) {                                           \
            const int cid = tid + 256 * p;                                      \
            const int r = cid >> 2, c = (cid & 3) * 8;                          \
            CP_ASYNC16(sb + (uint32_t)((128 + r) * HSTR + c) * 2u,              \
                       B + (size_t)(bn + r) * ldb + (k0) + c);                  \
        }                                                                       \
    } while (0)

    GFILL(0, 0);  CP_COMMIT();
    GFILL(1, 32); CP_COMMIT();
    GFILL(2, 64); CP_COMMIT();

    for (int i = 0; i < nch; i++) {
        const int s = i - (i / 3) * 3;
        CP_WAIT2();
        __syncthreads();

        const __half* SA = smh + s * STG_HALVES;
        const __half* SB = SA + 128 * HSTR;

        #pragma unroll
        for (int ks = 0; ks < 2; ks++) {
            const int o = ks * 16;
            unsigned af[4][4], bf[8][2];
            #pragma unroll
            for (int mi = 0; mi < 4; mi++) {
                const int r = wm + mi * 16;
                af[mi][0] = *reinterpret_cast<const unsigned*>(SA + (r + g    ) * HSTR + o + 2 * t    );
                af[mi][1] = *reinterpret_cast<const unsigned*>(SA + (r + g + 8) * HSTR + o + 2 * t    );
                af[mi][2] = *reinterpret_cast<const unsigned*>(SA + (r + g    ) * HSTR + o + 2 * t + 8);
                af[mi][3] = *reinterpret_cast<const unsigned*>(SA + (r + g + 8) * HSTR + o + 2 * t + 8);
            }
            #pragma unroll
            for (int ni = 0; ni < 8; ni++) {
                const int cb = wn + ni * 8 + g;
                bf[ni][0] = *reinterpret_cast<const unsigned*>(SB + cb * HSTR + o + 2 * t    );
                bf[ni][1] = *reinterpret_cast<const unsigned*>(SB + cb * HSTR + o + 2 * t + 8);
            }
            #pragma unroll
            for (int mi = 0; mi < 4; mi++)
                #pragma unroll
                for (int ni = 0; ni < 8; ni++)
                    MMA_F16(acc[mi][ni], af[mi][0], af[mi][1], af[mi][2], af[mi][3],
                            bf[ni][0], bf[ni][1]);
        }
        __syncthreads();

        if (i + 3 < nch) GFILL(s, (i + 3) * 32);
        CP_COMMIT();
    }
    #undef GFILL

    if (half_out) {
        __half* C = (__half*)Cv;
        #pragma unroll
        for (int mi = 0; mi < 4; mi++) {
            const size_t r0 = (size_t)(bm + wm + mi * 16 + g) * ldc + bn + wn;
            const size_t r1 = r0 + (size_t)8 * ldc;
            #pragma unroll
            for (int ni = 0; ni < 8; ni++) {
                const int cc = ni * 8 + 2 * t;
                *reinterpret_cast<unsigned*>(C + r0 + cc) = h2u(acc[mi][ni][0], acc[mi][ni][1]);
                *reinterpret_cast<unsigned*>(C + r1 + cc) = h2u(acc[mi][ni][2], acc[mi][ni][3]);
            }
        }
    } else {
        float* C = (float*)Cv;
        #pragma unroll
        for (int mi = 0; mi < 4; mi++) {
            const size_t r0 = (size_t)(bm + wm + mi * 16 + g) * ldc + bn + wn;
            const size_t r1 = r0 + (size_t)8 * ldc;
            #pragma unroll
            for (int ni = 0; ni < 8; ni++) {
                const int cc = ni * 8 + 2 * t;
                *reinterpret_cast<float2*>(C + r0 + cc) = make_float2(acc[mi][ni][0], acc[mi][ni][1]);
                *reinterpret_cast<float2*>(C + r1 + cc) = make_float2(acc[mi][ni][2], acc[mi][ni][3]);
            }
        }
    }
}

__global__ __launch_bounds__(256)
void gemm_h(const __half* __restrict__ A, const __half* __restrict__ B,
            void* __restrict__ C, int K, int lda, int ldb, int ldc, int half_out)
{
    gemm_core(A, B, C, K, lda, ldb, ldc, blockIdx.y * 128, blockIdx.x * 256, half_out);
}

__global__ __launch_bounds__(256)
void gemm_kv(const __half* __restrict__ xh, const __half* __restrict__ Wkh,
             const __half* __restrict__ Wvh, float* __restrict__ K, __half* __restrict__ VT)
{
    if (blockIdx.y == 0)
        gemm_core(xh, Wkh, K, HID, HID, HID, NKV * HD,
                  (blockIdx.x >> 2) * 128, (blockIdx.x & 3) * 256, 0);
    else
        gemm_core(Wvh, xh, VT, HID, HID, HID, T_SEQ,
                  (blockIdx.x >> 3) * 128, (blockIdx.x & 7) * 256, 1);
}

// ---------------------------------------------------------------------------
// Fused llama3-RoPE + fp16 conversion for Q AND K in one launch
// ---------------------------------------------------------------------------
__global__ void rope_qk(const float* __restrict__ Qin, __half* __restrict__ Qout,
                        const float* __restrict__ Kin, __half* __restrict__ Kout,
                        float qscale)
{
    const int t  = blockIdx.x;
    const int hy = blockIdx.y * 4 + threadIdx.y;
    const int i  = threadIdx.x;   // 0..63

    const float e   = (float)i * (1.0f / 64.0f);
    const float inv = exp2f(-18.931568569324174f * e);   // log2(500000)
    const float wavelen = 6.2831853071795865f / inv;
    float f;
    if (wavelen > 8192.0f) {
        f = inv * 0.125f;
    } else if (wavelen < 2048.0f) {
        f = inv;
    } else {
        const float smooth = (8192.0f / wavelen - 1.0f) * (1.0f / 3.0f);
        f = (1.0f - smooth) * 0.125f * inv + smooth * inv;
    }

    float s, c;
    sincosf((float)t * f, &s, &c);

    const float* in;
    __half* out;
    float scale;
    size_t base;
    if (hy < NH) {
        base  = (size_t)t * (NH * HD) + hy * HD;
        in    = Qin;  out = Qout;  scale = qscale;
    } else {
        const int h = hy - NH;
        base  = (size_t)t * (NKV * HD) + h * HD;
        in    = Kin;  out = Kout;  scale = 1.0f;
    }

    const float lo = in[base + i];
    const float hi = in[base + i + 64];
    out[base + i]      = __float2half_rn((lo * c - hi * s) * scale);
    out[base + i + 64] = __float2half_rn((hi * c + lo * s) * scale);
}

// ---------------------------------------------------------------------------
// Flash attention — R13 verbatim + skip-rescale fast path (bit-identical).
// 3 tiles, 2 CTAs/SM, single KV group. ldmatrix fragments, Q frags hoisted,
// log2 softmax (ex2.approx.f16x2), row sums via all-ones MMA. Q pre-scaled.
// ---------------------------------------------------------------------------
#define FH 136
#define FLASH_SMEM (3 * 128 * FH * 2)     // 104448 B -> 2 CTAs/SM
#define ONES_H2 0x3C003C00u
#define LDSM_PSTRIDE (16 * FH * 2)

__global__ __launch_bounds__(256)
void flash_attn(const __half* __restrict__ Qg, const __half* __restrict__ Kg,
                const __half* __restrict__ VTg, __half* __restrict__ Og)
{
    extern __shared__ __half fsm[];
    __half* Qs = fsm;
    const uint32_t qb = smem_u32(Qs);
    const uint32_t kb = qb + 128 * FH * 2;
    const uint32_t vb = kb + 128 * FH * 2;

    const int h  = blockIdx.y;
    const int ib = gridDim.x - 1 - blockIdx.x;   // heavy blocks first
    const int kv = h >> 2;
    const int tid  = threadIdx.x;
    const int lane = tid & 31;
    const int w    = tid >> 5;
    const int g    = lane >> 2;
    const int t    = lane & 3;
    const int wr   = w * 16;

    const uint32_t a_off = ((uint32_t)(wr + ((lane >> 3) & 1) * 8 + (lane & 7)) * FH
                            + ((lane >> 4) & 1) * 8) * 2u;
    const uint32_t b_off = ((uint32_t)(((lane >> 4) & 1) * 8 + (lane & 7)) * FH
                            + ((lane >> 3) & 1) * 8) * 2u;

    // Q tile prefetch, then hoist Q fragments into registers
    #pragma unroll
    for (int p = 0; p < 8; p++) {
        const int fidx = tid + 256 * p;
        const int r = fidx >> 4, c = (fidx & 15) * 8;
        CP_ASYNC16(qb + (uint32_t)(r * FH + c) * 2u,
                   Qg + (size_t)(ib * 128 + r) * (NH * HD) + h * HD + c);
    }
    CP_COMMIT();
    CP_WAIT0();
    __syncthreads();

    unsigned qf[8][4];
    #pragma unroll
    for (int ks = 0; ks < 8; ks++)
        LDSM4(qf[ks][0], qf[ks][1], qf[ks][2], qf[ks][3], qb + a_off + ks * 32);

    float m0 = -1e30f, m1 = -1e30f, l0 = 0.0f, l1 = 0.0f;
    float o[16][4];
    #pragma unroll
    for (int ni = 0; ni < 16; ni++)
        #pragma unroll
        for (int q = 0; q < 4; q++) o[ni][q] = 0.0f;

    for (int j = 0; j <= ib; j++) {
        __syncthreads();   // prior iteration done reading Ks/Vs
        #pragma unroll
        for (int p = 0; p < 8; p++) {
            const int fidx = tid + 256 * p;
            const int r = fidx >> 4, c = (fidx & 15) * 8;
            CP_ASYNC16(kb + (uint32_t)(r * FH + c) * 2u,
                       Kg + (size_t)(j * 128 + r) * (NKV * HD) + kv * HD + c);
            CP_ASYNC16(vb + (uint32_t)(r * FH + c) * 2u,
                       VTg + ((size_t)kv * HD + r) * T_SEQ + j * 128 + c);
        }
        CP_COMMIT();
        CP_WAIT0();
        __syncthreads();

        // S = Q*K^T in log2 units; K fragments via ldmatrix.x4
        float sc[16][4];
        #pragma unroll
        for (int ni = 0; ni < 16; ni++)
            #pragma unroll
            for (int q = 0; q < 4; q++) sc[ni][q] = 0.0f;

        #pragma unroll
        for (int ks = 0; ks < 8; ks++) {
            unsigned bf[16][2];
            #pragma unroll
            for (int p = 0; p < 8; p++)
                LDSM4(bf[2 * p][0], bf[2 * p][1], bf[2 * p + 1][0], bf[2 * p + 1][1],
                      kb + b_off + p * LDSM_PSTRIDE + ks * 32);
            #pragma unroll
            for (int ni = 0; ni < 16; ni++)
                MMA_F16(sc[ni], qf[ks][0], qf[ks][1], qf[ks][2], qf[ks][3],
                        bf[ni][0], bf[ni][1]);
        }

        // Causal mask on the diagonal block
        if (j == ib) {
            #pragma unroll
            for (int ni = 0; ni < 16; ni++) {
                const int c0 = ni * 8 + 2 * t;
                const int r0 = wr + g, r1 = wr + g + 8;
                if (c0     > r0) sc[ni][0] = -1e30f;
                if (c0 + 1 > r0) sc[ni][1] = -1e30f;
                if (c0     > r1) sc[ni][2] = -1e30f;
                if (c0 + 1 > r1) sc[ni][3] = -1e30f;
            }
        }

        // Row max (log2 domain)
        float bm0 = -1e30f, bm1 = -1e30f;
        #pragma unroll
        for (int ni = 0; ni < 16; ni++) {
            bm0 = fmaxf(bm0, fmaxf(sc[ni][0], sc[ni][1]));
            bm1 = fmaxf(bm1, fmaxf(sc[ni][2], sc[ni][3]));
        }
        bm0 = fmaxf(bm0, __shfl_xor_sync(0xffffffffu, bm0, 1));
        bm0 = fmaxf(bm0, __shfl_xor_sync(0xffffffffu, bm0, 2));
        bm1 = fmaxf(bm1, __shfl_xor_sync(0xffffffffu, bm1, 1));
        bm1 = fmaxf(bm1, __shfl_xor_sync(0xffffffffu, bm1, 2));

        // Skip-rescale fast path: if no row's max grew, al == 1 exactly.
        const bool need = __any_sync(0xffffffffu, (bm0 > m0) || (bm1 > m1));
        if (need) {
            const float mn0 = fmaxf(m0, bm0), mn1 = fmaxf(m1, bm1);
            const float al0 = ex2_f32(m0 - mn0), al1 = ex2_f32(m1 - mn1);
            #pragma unroll
            for (int ni = 0; ni < 16; ni++) {
                o[ni][0] *= al0; o[ni][1] *= al0;
                o[ni][2] *= al1; o[ni][3] *= al1;
            }
            l0 *= al0; l1 *= al1;
            m0 = mn0; m1 = mn1;
        }

        // P = 2^(s-m), pairwise fp16 MUFU
        unsigned ph[16][2];
        #pragma unroll
        for (int ni = 0; ni < 16; ni++) {
            ph[ni][0] = ex2_h2(h2u(sc[ni][0] - m0, sc[ni][1] - m0));
            ph[ni][1] = ex2_h2(h2u(sc[ni][2] - m1, sc[ni][3] - m1));
        }

        // O += P*V (V frags via ldmatrix.x4); row sums via all-ones MMA
        float ls[4] = {0.0f, 0.0f, 0.0f, 0.0f};
        #pragma unroll
        for (int kt = 0; kt < 8; kt++) {
            const unsigned a0 = ph[2 * kt    ][0];
            const unsigned a1 = ph[2 * kt    ][1];
            const unsigned a2 = ph[2 * kt + 1][0];
            const unsigned a3 = ph[2 * kt + 1][1];
            MMA_F16(ls, a0, a1, a2, a3, ONES_H2, ONES_H2);
            unsigned bf[16][2];
            #pragma unroll
            for (int p = 0; p < 8; p++)
                LDSM4(bf[2 * p][0], bf[2 * p][1], bf[2 * p + 1][0], bf[2 * p + 1][1],
                      vb + b_off + p * LDSM_PSTRIDE + kt * 32);
            #pragma unroll
            for (int ni = 0; ni < 16; ni++)
                MMA_F16(o[ni], a0, a1, a2, a3, bf[ni][0], bf[ni][1]);
        }
        l0 += ls[0];
        l1 += ls[2];
    }

    // Epilogue
    const float i0 = 1.0f / l0, i1 = 1.0f / l1;
    const size_t r0 = (size_t)(ib * 128 + wr + g) * (NH * HD) + h * HD;
    const size_t r1 = r0 + (size_t)8 * (NH * HD);
    #pragma unroll
    for (int ni = 0; ni < 16; ni++) {
        const int cc = ni * 8 + 2 * t;
        *reinterpret_cast<unsigned*>(Og + r0 + cc) = h2u(o[ni][0] * i0, o[ni][1] * i0);
        *reinterpret_cast<unsigned*>(Og + r1 + cc) = h2u(o[ni][2] * i1, o[ni][3] * i1);
    }
}

// ---------------------------------------------------------------------------
extern "C" void kernel_launch(void* const* d_in, const int* in_sizes, int n_in,
                              void* d_out, int out_size)
{
    const float* x  = (const float*)d_in[0];
    const float* Wq = (const float*)d_in[1];
    const float* Wk = (const float*)d_in[2];
    const float* Wv = (const float*)d_in[3];
    const float* Wo = (const float*)d_in[4];
    float* out = (float*)d_out;

    float *Q, *K;
    __half *xh, *Wqh, *Wkh, *Wvh, *Woh, *Qh, *Kh, *VTh, *Oh;
    cudaGetSymbolAddress((void**)&Q,   g_Q);
    cudaGetSymbolAddress((void**)&K,   g_K);
    cudaGetSymbolAddress((void**)&xh,  g_xh);
    cudaGetSymbolAddress((void**)&Wqh, g_Wqh);
    cudaGetSymbolAddress((void**)&Wkh, g_Wkh);
    cudaGetSymbolAddress((void**)&Wvh, g_Wvh);
    cudaGetSymbolAddress((void**)&Woh, g_Woh);
    cudaGetSymbolAddress((void**)&Qh,  g_Qh);
    cudaGetSymbolAddress((void**)&Kh,  g_Kh);
    cudaGetSymbolAddress((void**)&VTh, g_VTh);
    cudaGetSymbolAddress((void**)&Oh,  g_Oh);

    // All fp16 conversions in one launch
    cvt_all<<<24576, 256>>>((const float4*)x, (const float4*)Wq, (const float4*)Wk,
                            (const float4*)Wv, (const float4*)Wo,
                            (uint4*)xh, (uint4*)Wqh, (uint4*)Wkh, (uint4*)Wvh, (uint4*)Woh);

    cudaFuncSetAttribute(gemm_h,  cudaFuncAttributeMaxDynamicSharedMemorySize, GEMM_SMEM);
    cudaFuncSetAttribute(gemm_kv, cudaFuncAttributeMaxDynamicSharedMemorySize, GEMM_SMEM);
    cudaFuncSetAttribute(flash_attn, cudaFuncAttributeMaxDynamicSharedMemorySize, FLASH_SMEM);

    // Q = x*Wq^T (fp32 out, rope wants fp32)
    gemm_h<<<dim3(16, 16), 256, GEMM_SMEM>>>(xh, Wqh, Q, HID, HID, HID, 4096, 0);
    // K = x*Wk^T (fp32) and VT = Wv*x^T (fp16), fused
    gemm_kv<<<dim3(64, 2), 256, GEMM_SMEM>>>(xh, Wkh, Wvh, K, VTh);

    // RoPE (Q and K) fused with fp16 conversion; Q scale = log2(e)/sqrt(128)
    rope_qk<<<dim3(T_SEQ, (NH + NKV) / 4), dim3(64, 4)>>>(Q, Qh, K, Kh, 0.12751744f);

    // Fused causal attention
    flash_attn<<<dim3(16, NH), 256, FLASH_SMEM>>>(Qh, Kh, VTh, Oh);

    // out = O*Wo^T (fp32 out)
    gemm_h<<<dim3(16, 16), 256, GEMM_SMEM>>>(Oh, Woh, out, 4096, 4096, 4096, HID, 0);
}

// round 17
// speedup vs baseline: 1.5034x; 1.0257x over previous
#include <cuda_runtime.h>
#include <cuda_fp16.h>
#include <math.h>
#include <stdint.h>

#define T_SEQ 2048
#define HID 4096
#define NH 32
#define NKV 8
#define HD 128

// ---------------- scratch (__device__ globals; no allocations) -------------
__device__ float  g_Q  [(size_t)T_SEQ * NH * HD];     // fp32 Q (pre-rope)
__device__ float  g_K  [(size_t)T_SEQ * NKV * HD];    // fp32 K (pre-rope)
__device__ __half g_xh [(size_t)T_SEQ * HID];
__device__ __half g_Wqh[(size_t)NH * HD * HID];
__device__ __half g_Wkh[(size_t)NKV * HD * HID];
__device__ __half g_Wvh[(size_t)NKV * HD * HID];
__device__ __half g_Woh[(size_t)HID * NH * HD];
__device__ __half g_Qh [(size_t)T_SEQ * NH * HD];     // roped, scaled log2e/sqrt(128)
__device__ __half g_Kh [(size_t)T_SEQ * NKV * HD];    // roped
__device__ __half g_VTh[(size_t)NKV * HD * T_SEQ];    // V^T [h][d][t]
__device__ __half g_Oh [(size_t)T_SEQ * NH * HD];

__device__ __forceinline__ uint32_t smem_u32(const void* p) {
    uint32_t a;
    asm("{ .reg .u64 t; cvta.to.shared.u64 t, %1; cvt.u32.u64 %0, t; }"
        : "=r"(a) : "l"(p));
    return a;
}
__device__ __forceinline__ unsigned h2u(float a, float b) {
    __half2 h = __floats2half2_rn(a, b);
    return *reinterpret_cast<unsigned*>(&h);
}
__device__ __forceinline__ unsigned ex2_h2(unsigned x) {
    unsigned r;
    asm("ex2.approx.f16x2 %0, %1;" : "=r"(r) : "r"(x));
    return r;
}
__device__ __forceinline__ float ex2_f32(float x) {
    float r;
    asm("ex2.approx.f32 %0, %1;" : "=f"(r) : "f"(x));
    return r;
}

#define MMA_F16(d, a0,a1,a2,a3, b0,b1)                                        \
    asm volatile(                                                             \
        "mma.sync.aligned.m16n8k16.row.col.f32.f16.f16.f32 "                  \
        "{%0,%1,%2,%3}, {%4,%5,%6,%7}, {%8,%9}, {%0,%1,%2,%3};"               \
        : "+f"((d)[0]), "+f"((d)[1]), "+f"((d)[2]), "+f"((d)[3])              \
        : "r"(a0), "r"(a1), "r"(a2), "r"(a3), "r"(b0), "r"(b1))

#define LDSM4(r0, r1, r2, r3, addr)                                           \
    asm volatile("ldmatrix.sync.aligned.m8n8.x4.shared.b16 {%0,%1,%2,%3}, [%4];" \
        : "=r"(r0), "=r"(r1), "=r"(r2), "=r"(r3) : "r"(addr))

#define CP_ASYNC16(dst, src) \
    asm volatile("cp.async.cg.shared.global [%0], [%1], 16;" :: "r"(dst), "l"(src))
#define CP_COMMIT()  asm volatile("cp.async.commit_group;" ::: "memory")
#define CP_WAIT2()   asm volatile("cp.async.wait_group 2;" ::: "memory")
#define CP_WAIT0()   asm volatile("cp.async.wait_group 0;" ::: "memory")

// ---------------------------------------------------------------------------
// Fused fp32 -> fp16 conversion of all 5 inputs in ONE launch.
// ---------------------------------------------------------------------------
#define SEG_X  1048576L
#define SEG_WQ (SEG_X + 2097152L)
#define SEG_WK (SEG_WQ + 524288L)
#define SEG_WV (SEG_WK + 524288L)

__global__ void cvt_all(const float4* __restrict__ x,  const float4* __restrict__ wq,
                        const float4* __restrict__ wk, const float4* __restrict__ wv,
                        const float4* __restrict__ wo,
                        uint4* __restrict__ xh,  uint4* __restrict__ wqh,
                        uint4* __restrict__ wkh, uint4* __restrict__ wvh,
                        uint4* __restrict__ woh)
{
    const long i = (long)blockIdx.x * blockDim.x + threadIdx.x;
    const float4* in;
    uint4* out;
    long off;
    if (i < SEG_X)       { in = x;  out = xh;  off = 0; }
    else if (i < SEG_WQ) { in = wq; out = wqh; off = SEG_X; }
    else if (i < SEG_WK) { in = wk; out = wkh; off = SEG_WQ; }
    else if (i < SEG_WV) { in = wv; out = wvh; off = SEG_WK; }
    else                 { in = wo; out = woh; off = SEG_WV; }
    const long j = i - off;
    float4 v0 = in[2 * j];
    float4 v1 = in[2 * j + 1];
    uint4 o;
    o.x = h2u(v0.x, v0.y);
    o.y = h2u(v0.z, v0.w);
    o.z = h2u(v1.x, v1.y);
    o.w = h2u(v1.z, v1.w);
    out[j] = o;
}

// ---------------------------------------------------------------------------
// FP16 GEMM core (R13 verbatim — scalar fragment LDS, at HMMA pipe floor)
// ---------------------------------------------------------------------------
#define HSTR 40
#define STG_HALVES ((128 + 256) * HSTR)
#define STG_BYTES  (STG_HALVES * 2)
#define GEMM_SMEM  (3 * STG_BYTES)

__device__ __forceinline__ void gemm_core(
    const __half* __restrict__ A, const __half* __restrict__ B, void* __restrict__ Cv,
    int K, int lda, int ldb, int ldc, int bm, int bn, int half_out)
{
    extern __shared__ __half smh[];
    const uint32_t smb = smem_u32(smh);

    const int tid  = threadIdx.x;
    const int lane = tid & 31;
    const int w    = tid >> 5;
    const int g    = lane >> 2;
    const int t    = lane & 3;
    const int wm   = (w >> 2) * 64;
    const int wn   = (w & 3) * 64;

    float acc[4][8][4];
    #pragma unroll
    for (int mi = 0; mi < 4; mi++)
        #pragma unroll
        for (int ni = 0; ni < 8; ni++)
            #pragma unroll
            for (int q = 0; q < 4; q++) acc[mi][ni][q] = 0.0f;

    const int nch = K >> 5;

    #define GFILL(stage, k0) do {                                              \
        const uint32_t sb = smb + (stage) * STG_BYTES;                          \
        _Pragma("unroll")                                                       \
        for (int p = 0; p < 2; p++) {                                           \
            const int cid = tid + 256 * p;                                      \
            const int r = cid >> 2, c = (cid & 3) * 8;                          \
            CP_ASYNC16(sb + (uint32_t)(r * HSTR + c) * 2u,                      \
                       A + (size_t)(bm + r) * lda + (k0) + c);                  \
        }                                                                       \
        _Pragma("unroll")                                                       \
        for (int p = 0; p < 4; p++) {                                           \
            const int cid = tid + 256 * p;                                      \
            const int r = cid >> 2, c = (cid & 3) * 8;                          \
            CP_ASYNC16(sb + (uint32_t)((128 + r) * HSTR + c) * 2u,              \
                       B + (size_t)(bn + r) * ldb + (k0) + c);                  \
        }                                                                       \
    } while (0)

    GFILL(0, 0);  CP_COMMIT();
    GFILL(1, 32); CP_COMMIT();
    GFILL(2, 64); CP_COMMIT();

    for (int i = 0; i < nch; i++) {
        const int s = i - (i / 3) * 3;
        CP_WAIT2();
        __syncthreads();

        const __half* SA = smh + s * STG_HALVES;
        const __half* SB = SA + 128 * HSTR;

        #pragma unroll
        for (int ks = 0; ks < 2; ks++) {
            const int o = ks * 16;
            unsigned af[4][4], bf[8][2];
            #pragma unroll
            for (int mi = 0; mi < 4; mi++) {
                const int r = wm + mi * 16;
                af[mi][0] = *reinterpret_cast<const unsigned*>(SA + (r + g    ) * HSTR + o + 2 * t    );
                af[mi][1] = *reinterpret_cast<const unsigned*>(SA + (r + g + 8) * HSTR + o + 2 * t    );
                af[mi][2] = *reinterpret_cast<const unsigned*>(SA + (r + g    ) * HSTR + o + 2 * t + 8);
                af[mi][3] = *reinterpret_cast<const unsigned*>(SA + (r + g + 8) * HSTR + o + 2 * t + 8);
            }
            #pragma unroll
            for (int ni = 0; ni < 8; ni++) {
                const int cb = wn + ni * 8 + g;
                bf[ni][0] = *reinterpret_cast<const unsigned*>(SB + cb * HSTR + o + 2 * t    );
                bf[ni][1] = *reinterpret_cast<const unsigned*>(SB + cb * HSTR + o + 2 * t + 8);
            }
            #pragma unroll
            for (int mi = 0; mi < 4; mi++)
                #pragma unroll
                for (int ni = 0; ni < 8; ni++)
                    MMA_F16(acc[mi][ni], af[mi][0], af[mi][1], af[mi][2], af[mi][3],
                            bf[ni][0], bf[ni][1]);
        }
        __syncthreads();

        if (i + 3 < nch) GFILL(s, (i + 3) * 32);
        CP_COMMIT();
    }
    #undef GFILL

    if (half_out) {
        __half* C = (__half*)Cv;
        #pragma unroll
        for (int mi = 0; mi < 4; mi++) {
            const size_t r0 = (size_t)(bm + wm + mi * 16 + g) * ldc + bn + wn;
            const size_t r1 = r0 + (size_t)8 * ldc;
            #pragma unroll
            for (int ni = 0; ni < 8; ni++) {
                const int cc = ni * 8 + 2 * t;
                *reinterpret_cast<unsigned*>(C + r0 + cc) = h2u(acc[mi][ni][0], acc[mi][ni][1]);
                *reinterpret_cast<unsigned*>(C + r1 + cc) = h2u(acc[mi][ni][2], acc[mi][ni][3]);
            }
        }
    } else {
        float* C = (float*)Cv;
        #pragma unroll
        for (int mi = 0; mi < 4; mi++) {
            const size_t r0 = (size_t)(bm + wm + mi * 16 + g) * ldc + bn + wn;
            const size_t r1 = r0 + (size_t)8 * ldc;
            #pragma unroll
            for (int ni = 0; ni < 8; ni++) {
                const int cc = ni * 8 + 2 * t;
                *reinterpret_cast<float2*>(C + r0 + cc) = make_float2(acc[mi][ni][0], acc[mi][ni][1]);
                *reinterpret_cast<float2*>(C + r1 + cc) = make_float2(acc[mi][ni][2], acc[mi][ni][3]);
            }
        }
    }
}

__global__ __launch_bounds__(256)
void gemm_h(const __half* __restrict__ A, const __half* __restrict__ B,
            void* __restrict__ C, int K, int lda, int ldb, int ldc, int half_out)
{
    gemm_core(A, B, C, K, lda, ldb, ldc, blockIdx.y * 128, blockIdx.x * 256, half_out);
}

// All three projections in one launch: 256 Q-CTAs + 64 K-CTAs + 64 VT-CTAs
__global__ __launch_bounds__(256)
void gemm_qkv(const __half* __restrict__ xh, const __half* __restrict__ Wqh,
              const __half* __restrict__ Wkh, const __half* __restrict__ Wvh,
              float* __restrict__ Q, float* __restrict__ K, __half* __restrict__ VT)
{
    const int b = blockIdx.x;
    if (b < 256)        // Q = x*Wq^T [2048,4096]
        gemm_core(xh, Wqh, Q, HID, HID, HID, 4096, (b >> 4) * 128, (b & 15) * 256, 0);
    else if (b < 320) { // K = x*Wk^T [2048,1024]
        const int b2 = b - 256;
        gemm_core(xh, Wkh, K, HID, HID, HID, 1024, (b2 >> 2) * 128, (b2 & 3) * 256, 0);
    } else {            // VT = Wv*x^T [1024,2048]
        const int b3 = b - 320;
        gemm_core(Wvh, xh, VT, HID, HID, HID, T_SEQ, (b3 >> 3) * 128, (b3 & 7) * 256, 1);
    }
}

// ---------------------------------------------------------------------------
// Fused llama3-RoPE + fp16 conversion for Q AND K in one launch
// ---------------------------------------------------------------------------
__global__ void rope_qk(const float* __restrict__ Qin, __half* __restrict__ Qout,
                        const float* __restrict__ Kin, __half* __restrict__ Kout,
                        float qscale)
{
    const int t  = blockIdx.x;
    const int hy = blockIdx.y * 4 + threadIdx.y;
    const int i  = threadIdx.x;   // 0..63

    const float e   = (float)i * (1.0f / 64.0f);
    const float inv = exp2f(-18.931568569324174f * e);   // log2(500000)
    const float wavelen = 6.2831853071795865f / inv;
    float f;
    if (wavelen > 8192.0f) {
        f = inv * 0.125f;
    } else if (wavelen < 2048.0f) {
        f = inv;
    } else {
        const float smooth = (8192.0f / wavelen - 1.0f) * (1.0f / 3.0f);
        f = (1.0f - smooth) * 0.125f * inv + smooth * inv;
    }

    float s, c;
    sincosf((float)t * f, &s, &c);

    const float* in;
    __half* out;
    float scale;
    size_t base;
    if (hy < NH) {
        base  = (size_t)t * (NH * HD) + hy * HD;
        in    = Qin;  out = Qout;  scale = qscale;
    } else {
        const int h = hy - NH;
        base  = (size_t)t * (NKV * HD) + h * HD;
        in    = Kin;  out = Kout;  scale = 1.0f;
    }

    const float lo = in[base + i];
    const float hi = in[base + i + 64];
    out[base + i]      = __float2half_rn((lo * c - hi * s) * scale);
    out[base + i + 64] = __float2half_rn((hi * c + lo * s) * scale);
}

// ---------------------------------------------------------------------------
// Flash attention — R13 verbatim. 3 tiles, 2 CTAs/SM, single KV group.
// ldmatrix fragments, Q frags hoisted, log2 softmax (ex2.approx.f16x2),
// row sums via all-ones MMA. Q pre-scaled by log2e/sqrt(128).
// ---------------------------------------------------------------------------
#define FH 136
#define FLASH_SMEM (3 * 128 * FH * 2)     // 104448 B -> 2 CTAs/SM
#define ONES_H2 0x3C003C00u
#define LDSM_PSTRIDE (16 * FH * 2)

__global__ __launch_bounds__(256)
void flash_attn(const __half* __restrict__ Qg, const __half* __restrict__ Kg,
                const __half* __restrict__ VTg, __half* __restrict__ Og)
{
    extern __shared__ __half fsm[];
    __half* Qs = fsm;
    const uint32_t qb = smem_u32(Qs);
    const uint32_t kb = qb + 128 * FH * 2;
    const uint32_t vb = kb + 128 * FH * 2;

    const int h  = blockIdx.y;
    const int ib = gridDim.x - 1 - blockIdx.x;   // heavy blocks first
    const int kv = h >> 2;
    const int tid  = threadIdx.x;
    const int lane = tid & 31;
    const int w    = tid >> 5;
    const int g    = lane >> 2;
    const int t    = lane & 3;
    const int wr   = w * 16;

    const uint32_t a_off = ((uint32_t)(wr + ((lane >> 3) & 1) * 8 + (lane & 7)) * FH
                            + ((lane >> 4) & 1) * 8) * 2u;
    const uint32_t b_off = ((uint32_t)(((lane >> 4) & 1) * 8 + (lane & 7)) * FH
                            + ((lane >> 3) & 1) * 8) * 2u;

    // Q tile prefetch, then hoist Q fragments into registers
    #pragma unroll
    for (int p = 0; p < 8; p++) {
        const int fidx = tid + 256 * p;
        const int r = fidx >> 4, c = (fidx & 15) * 8;
        CP_ASYNC16(qb + (uint32_t)(r * FH + c) * 2u,
                   Qg + (size_t)(ib * 128 + r) * (NH * HD) + h * HD + c);
    }
    CP_COMMIT();
    CP_WAIT0();
    __syncthreads();

    unsigned qf[8][4];
    #pragma unroll
    for (int ks = 0; ks < 8; ks++)
        LDSM4(qf[ks][0], qf[ks][1], qf[ks][2], qf[ks][3], qb + a_off + ks * 32);

    float m0 = -1e30f, m1 = -1e30f, l0 = 0.0f, l1 = 0.0f;
    float o[16][4];
    #pragma unroll
    for (int ni = 0; ni < 16; ni++)
        #pragma unroll
        for (int q = 0; q < 4; q++) o[ni][q] = 0.0f;

    for (int j = 0; j <= ib; j++) {
        __syncthreads();   // prior iteration done reading Ks/Vs
        #pragma unroll
        for (int p = 0; p < 8; p++) {
            const int fidx = tid + 256 * p;
            const int r = fidx >> 4, c = (fidx & 15) * 8;
            CP_ASYNC16(kb + (uint32_t)(r * FH + c) * 2u,
                       Kg + (size_t)(j * 128 + r) * (NKV * HD) + kv * HD + c);
            CP_ASYNC16(vb + (uint32_t)(r * FH + c) * 2u,
                       VTg + ((size_t)kv * HD + r) * T_SEQ + j * 128 + c);
        }
        CP_COMMIT();
        CP_WAIT0();
        __syncthreads();

        // S = Q*K^T in log2 units; K fragments via ldmatrix.x4
        float sc[16][4];
        #pragma unroll
        for (int ni = 0; ni < 16; ni++)
            #pragma unroll
            for (int q = 0; q < 4; q++) sc[ni][q] = 0.0f;

        #pragma unroll
        for (int ks = 0; ks < 8; ks++) {
            unsigned bf[16][2];
            #pragma unroll
            for (int p = 0; p < 8; p++)
                LDSM4(bf[2 * p][0], bf[2 * p][1], bf[2 * p + 1][0], bf[2 * p + 1][1],
                      kb + b_off + p * LDSM_PSTRIDE + ks * 32);
            #pragma unroll
            for (int ni = 0; ni < 16; ni++)
                MMA_F16(sc[ni], qf[ks][0], qf[ks][1], qf[ks][2], qf[ks][3],
                        bf[ni][0], bf[ni][1]);
        }

        // Causal mask on the diagonal block
        if (j == ib) {
            #pragma unroll
            for (int ni = 0; ni < 16; ni++) {
                const int c0 = ni * 8 + 2 * t;
                const int r0 = wr + g, r1 = wr + g + 8;
                if (c0     > r0) sc[ni][0] = -1e30f;
                if (c0 + 1 > r0) sc[ni][1] = -1e30f;
                if (c0     > r1) sc[ni][2] = -1e30f;
                if (c0 + 1 > r1) sc[ni][3] = -1e30f;
            }
        }

        // Row max (log2 domain)
        float bm0 = -1e30f, bm1 = -1e30f;
        #pragma unroll
        for (int ni = 0; ni < 16; ni++) {
            bm0 = fmaxf(bm0, fmaxf(sc[ni][0], sc[ni][1]));
            bm1 = fmaxf(bm1, fmaxf(sc[ni][2], sc[ni][3]));
        }
        bm0 = fmaxf(bm0, __shfl_xor_sync(0xffffffffu, bm0, 1));
        bm0 = fmaxf(bm0, __shfl_xor_sync(0xffffffffu, bm0, 2));
        bm1 = fmaxf(bm1, __shfl_xor_sync(0xffffffffu, bm1, 1));
        bm1 = fmaxf(bm1, __shfl_xor_sync(0xffffffffu, bm1, 2));

        const float mn0 = fmaxf(m0, bm0), mn1 = fmaxf(m1, bm1);
        const float al0 = ex2_f32(m0 - mn0), al1 = ex2_f32(m1 - mn1);
        m0 = mn0; m1 = mn1;

        // P = 2^(s-m), pairwise fp16 MUFU
        unsigned ph[16][2];
        #pragma unroll
        for (int ni = 0; ni < 16; ni++) {
            ph[ni][0] = ex2_h2(h2u(sc[ni][0] - mn0, sc[ni][1] - mn0));
            ph[ni][1] = ex2_h2(h2u(sc[ni][2] - mn1, sc[ni][3] - mn1));
        }

        #pragma unroll
        for (int ni = 0; ni < 16; ni++) {
            o[ni][0] *= al0; o[ni][1] *= al0;
            o[ni][2] *= al1; o[ni][3] *= al1;
        }

        // O += P*V (V frags via ldmatrix.x4); row sums via all-ones MMA
        float ls[4] = {0.0f, 0.0f, 0.0f, 0.0f};
        #pragma unroll
        for (int kt = 0; kt < 8; kt++) {
            const unsigned a0 = ph[2 * kt    ][0];
            const unsigned a1 = ph[2 * kt    ][1];
            const unsigned a2 = ph[2 * kt + 1][0];
            const unsigned a3 = ph[2 * kt + 1][1];
            MMA_F16(ls, a0, a1, a2, a3, ONES_H2, ONES_H2);
            unsigned bf[16][2];
            #pragma unroll
            for (int p = 0; p < 8; p++)
                LDSM4(bf[2 * p][0], bf[2 * p][1], bf[2 * p + 1][0], bf[2 * p + 1][1],
                      vb + b_off + p * LDSM_PSTRIDE + kt * 32);
            #pragma unroll
            for (int ni = 0; ni < 16; ni++)
                MMA_F16(o[ni], a0, a1, a2, a3, bf[ni][0], bf[ni][1]);
        }
        l0 = l0 * al0 + ls[0];
        l1 = l1 * al1 + ls[2];
    }

    // Epilogue
    const float i0 = 1.0f / l0, i1 = 1.0f / l1;
    const size_t r0 = (size_t)(ib * 128 + wr + g) * (NH * HD) + h * HD;
    const size_t r1 = r0 + (size_t)8 * (NH * HD);
    #pragma unroll
    for (int ni = 0; ni < 16; ni++) {
        const int cc = ni * 8 + 2 * t;
        *reinterpret_cast<unsigned*>(Og + r0 + cc) = h2u(o[ni][0] * i0, o[ni][1] * i0);
        *reinterpret_cast<unsigned*>(Og + r1 + cc) = h2u(o[ni][2] * i1, o[ni][3] * i1);
    }
}

// ---------------------------------------------------------------------------
extern "C" void kernel_launch(void* const* d_in, const int* in_sizes, int n_in,
                              void* d_out, int out_size)
{
    const float* x  = (const float*)d_in[0];
    const float* Wq = (const float*)d_in[1];
    const float* Wk = (const float*)d_in[2];
    const float* Wv = (const float*)d_in[3];
    const float* Wo = (const float*)d_in[4];
    float* out = (float*)d_out;

    float *Q, *K;
    __half *xh, *Wqh, *Wkh, *Wvh, *Woh, *Qh, *Kh, *VTh, *Oh;
    cudaGetSymbolAddress((void**)&Q,   g_Q);
    cudaGetSymbolAddress((void**)&K,   g_K);
    cudaGetSymbolAddress((void**)&xh,  g_xh);
    cudaGetSymbolAddress((void**)&Wqh, g_Wqh);
    cudaGetSymbolAddress((void**)&Wkh, g_Wkh);
    cudaGetSymbolAddress((void**)&Wvh, g_Wvh);
    cudaGetSymbolAddress((void**)&Woh, g_Woh);
    cudaGetSymbolAddress((void**)&Qh,  g_Qh);
    cudaGetSymbolAddress((void**)&Kh,  g_Kh);
    cudaGetSymbolAddress((void**)&VTh, g_VTh);
    cudaGetSymbolAddress((void**)&Oh,  g_Oh);

    // All fp16 conversions in one launch
    cvt_all<<<24576, 256>>>((const float4*)x, (const float4*)Wq, (const float4*)Wk,
                            (const float4*)Wv, (const float4*)Wo,
                            (uint4*)xh, (uint4*)Wqh, (uint4*)Wkh, (uint4*)Wvh, (uint4*)Woh);

    cudaFuncSetAttribute(gemm_qkv, cudaFuncAttributeMaxDynamicSharedMemorySize, GEMM_SMEM);
    cudaFuncSetAttribute(gemm_h,   cudaFuncAttributeMaxDynamicSharedMemorySize, GEMM_SMEM);
    cudaFuncSetAttribute(flash_attn, cudaFuncAttributeMaxDynamicSharedMemorySize, FLASH_SMEM);

    // All three projections in ONE launch (384 CTAs; Q/K fp32 out, VT fp16)
    gemm_qkv<<<384, 256, GEMM_SMEM>>>(xh, Wqh, Wkh, Wvh, Q, K, VTh);

    // RoPE (Q and K) fused with fp16 conversion; Q scale = log2(e)/sqrt(128)
    rope_qk<<<dim3(T_SEQ, (NH + NKV) / 4), dim3(64, 4)>>>(Q, Qh, K, Kh, 0.12751744f);

    // Fused causal attention
    flash_attn<<<dim3(16, NH), 256, FLASH_SMEM>>>(Qh, Kh, VTh, Oh);

    // out = O*Wo^T (fp32 out)
    gemm_h<<<dim3(16, 16), 256, GEMM_SMEM>>>(Oh, Woh, out, 4096, 4096, 4096, HID, 0);
}